// round 6
// baseline (speedup 1.0000x reference)
#include <cuda_runtime.h>
#include <cuda_fp16.h>
#include <cstdint>

#define HN       128
#define BATCH    1024
#define SEQT     512
#define CL       8            // CTAs per cluster
#define MROWS    64           // batch rows per cluster
#define NTHREADS 256

#define SAW      132          // A-tile row stride in 32-bit words (264 fp16 = 528 B)

// ---- shared memory layout (32-bit word offsets) ----
#define OF_A     0                       // A tile [64][264 fp16] = 8448 words
#define OF_B1    (64 * SAW)              // layer-1 B frags: 4096 words (16 KB)
#define OF_B2    (OF_B1 + 4096)          // layer-2 B frags: 8192 words (32 KB)
#define OF_WX    (OF_B2 + 8192)          // Wih1 slice   [64] floats
#define OF_BB1   (OF_WX + 64)            // bih1+bhh1    [64] floats
#define OF_BB2   (OF_BB1 + 64)           // bih2+bhh2    [64] floats
#define SMEM_WORDS (OF_BB2 + 64)
#define SMEM_BYTES (SMEM_WORDS * 4)      // 83,712 B

// ---- device scratch (allocation-free) ----
__device__ float    g_xT[SEQT * BATCH];      // x transposed to [T, B]
__device__ uint32_t g_h[2][BATCH * 128];     // double-buffered: per row 128 words = [h1 | h2] fp16

// ======================= helpers =======================
__device__ __forceinline__ uint32_t smem_u32(const void* p) {
    uint32_t a;
    asm("{ .reg .u64 t; cvta.to.shared.u64 t, %1; cvt.u32.u64 %0, t; }" : "=r"(a) : "l"(p));
    return a;
}
#define CLUSTER_ARRIVE() asm volatile("barrier.cluster.arrive.aligned;" ::: "memory")
#define CLUSTER_WAIT()   asm volatile("barrier.cluster.wait.aligned;" ::: "memory")

__device__ __forceinline__ void mmaf16(float* d, const uint32_t* a, uint32_t b0, uint32_t b1) {
    asm volatile(
        "mma.sync.aligned.m16n8k16.row.col.f32.f16.f16.f32 "
        "{%0,%1,%2,%3}, {%4,%5,%6,%7}, {%8,%9}, {%0,%1,%2,%3};"
        : "+f"(d[0]), "+f"(d[1]), "+f"(d[2]), "+f"(d[3])
        : "r"(a[0]), "r"(a[1]), "r"(a[2]), "r"(a[3]), "r"(b0), "r"(b1));
}
__device__ __forceinline__ void ldmA(uint32_t* r, uint32_t addr) {
    asm volatile("ldmatrix.sync.aligned.m8n8.x4.shared.b16 {%0,%1,%2,%3}, [%4];"
                 : "=r"(r[0]), "=r"(r[1]), "=r"(r[2]), "=r"(r[3]) : "r"(addr));
}
// sigmoid via tanh.approx (1 MUFU + 2 FMA); g-gate & cell tanh stay precise
__device__ __forceinline__ float tanha(float x) {
    float y; asm("tanh.approx.f32 %0, %1;" : "=f"(y) : "f"(x)); return y;
}
__device__ __forceinline__ float sigfa(float x) {
    return fmaf(0.5f, tanha(0.5f * x), 0.5f);
}
__device__ __forceinline__ float tanhe(float x) {
    float e = __expf(-2.0f * x);
    return 2.0f * __fdividef(1.0f, 1.0f + e) - 1.0f;
}

// ======================= kernels =======================
__global__ void xT_kernel(const float* __restrict__ x) {
    int i = blockIdx.x * blockDim.x + threadIdx.x;   // i = t*1024 + b (coalesced writes)
    if (i < BATCH * SEQT) {
        int tt = i >> 10, b = i & 1023;
        g_xT[i] = x[b * SEQT + tt];
    }
}

extern "C" __global__ void __launch_bounds__(NTHREADS, 1) __cluster_dims__(CL, 1, 1)
lstm2_kernel(const float* __restrict__ Wih1, const float* __restrict__ Whh1,
             const float* __restrict__ bih1, const float* __restrict__ bhh1,
             const float* __restrict__ Wih2, const float* __restrict__ Whh2,
             const float* __restrict__ bih2, const float* __restrict__ bhh2,
             const float* __restrict__ Wl,   const float* __restrict__ bl,
             float* __restrict__ out)
{
    extern __shared__ uint32_t sm[];
    const int tid  = threadIdx.x;
    const int lane = tid & 31;
    const int wid  = tid >> 5;          // 0..7
    const int g    = lane >> 2;
    const int tq   = lane & 3;
    const int mq   = wid >> 1;          // 0..3 : M16 tile
    const int qh   = wid & 1;           // 0..1 : 8-dim half of the 16-dim slice
    const int mbase = mq * 16;
    const int rank = blockIdx.x & (CL - 1);
    const int b0   = (blockIdx.x / CL) * MROWS;

    float* WX  = (float*)(sm + OF_WX);
    float* BB1 = (float*)(sm + OF_BB1);
    float* BB2 = (float*)(sm + OF_BB2);

    // ---- pack weight slices into fp16 mma-fragment order ----
    // Consumption: uint4 U = ((q2*KTP + ktp)*2 + p)*32 + lane  -> word = 4*U + j
    // decode: j = idx&3, lane = (idx>>2)&31, p = (idx>>7)&1, ktp next, q2 top.
    // Fragment: gate = p*2 + (j>>1), reg = j&1;
    // B[k][n]: k0 = ktp*16 + reg*8 + 2*(lane&3), n = q2*8 + (lane>>2)
    for (int idx = tid; idx < 4096; idx += NTHREADS) {          // layer 1 (K=128)
        int j = idx & 3, ln = (idx >> 2) & 31, p = (idx >> 7) & 1;
        int ktp = (idx >> 8) & 7, q2 = idx >> 11;
        int gate = p * 2 + (j >> 1), reg = j & 1;
        int gg = ln >> 2, ttq = ln & 3;
        int k0 = ktp * 16 + reg * 8 + 2 * ttq;
        int gr = gate * HN + rank * 16 + q2 * 8 + gg;
        __half2 hv = __floats2half2_rn(Whh1[gr * HN + k0], Whh1[gr * HN + k0 + 1]);
        sm[OF_B1 + idx] = *(uint32_t*)&hv;
    }
    for (int idx = tid; idx < 8192; idx += NTHREADS) {          // layer 2 (K=256)
        int j = idx & 3, ln = (idx >> 2) & 31, p = (idx >> 7) & 1;
        int ktp = (idx >> 8) & 15, q2 = idx >> 12;
        int gate = p * 2 + (j >> 1), reg = j & 1;
        int gg = ln >> 2, ttq = ln & 3;
        int k0 = ktp * 16 + reg * 8 + 2 * ttq;
        int gr = gate * HN + rank * 16 + q2 * 8 + gg;
        float w0 = (k0 < HN)     ? Wih2[gr * HN + k0]     : Whh2[gr * HN + k0 - HN];
        float w1 = (k0 + 1 < HN) ? Wih2[gr * HN + k0 + 1] : Whh2[gr * HN + k0 + 1 - HN];
        __half2 hv = __floats2half2_rn(w0, w1);
        sm[OF_B2 + idx] = *(uint32_t*)&hv;
    }
    if (tid < 64) {
        int gt = tid >> 4, q = tid & 15;
        int gr = gt * HN + rank * 16 + q;
        WX[tid]  = Wih1[gr];
        BB1[tid] = bih1[gr] + bhh1[gr];
        BB2[tid] = bih2[gr] + bhh2[gr];
    }
    for (int i = tid; i < 64 * SAW; i += NTHREADS) sm[OF_A + i] = 0u;   // h1=h2=0
    __syncthreads();

    // per-thread rows (2 per layer-tile) and ldmatrix address
    int rows[2];
    rows[0] = mbase + g;
    rows[1] = mbase + g + 8;

    const uint32_t sbA = smem_u32(sm) + OF_A * 4;
    const int row_in = mbase + (lane & 7) + ((lane >> 3) & 1) * 8;
    const uint32_t lmaddr = sbA + (uint32_t)row_in * 528u + ((lane >> 4) & 1) * 16u;

    const uint4* Bq1 = (const uint4*)(sm + OF_B1);
    const uint4* Bq2 = (const uint4*)(sm + OF_B2);

    float c1[4], c2[4];
#pragma unroll
    for (int i = 0; i < 4; i++) { c1[i] = 0.f; c2[i] = 0.f; }

    // gather indices: 4 threads per row, 8 uint4 each
    const int gr_row = tid >> 2, gr_q = tid & 3;

    for (int n = 0; n <= SEQT; n++) {
        uint32_t* ghw = g_h[n & 1];     // this iteration's exchange buffer

        // prefetch x(n) early (consumed after MMA)
        float xtv[2];
        if (n < SEQT) {
#pragma unroll
            for (int e = 0; e < 2; e++) xtv[e] = __ldcg(&g_xT[n * BATCH + b0 + rows[e]]);
        }

        float acc1[4][4], acc2[4][4];
#pragma unroll
        for (int a1 = 0; a1 < 4; a1++)
#pragma unroll
            for (int a3 = 0; a3 < 4; a3++) { acc1[a1][a3] = 0.f; acc2[a1][a3] = 0.f; }

        // ---- k chunks 0..7 : A cols 0:128 = h1(n-1), feeds gates1 AND gates2 ----
#pragma unroll 2
        for (int ktp = 0; ktp < 8; ktp++) {
            uint4 b1a = Bq1[((qh * 8 + ktp) * 2 + 0) * 32 + lane];
            uint4 b1b = Bq1[((qh * 8 + ktp) * 2 + 1) * 32 + lane];
            uint4 b2a = Bq2[((qh * 16 + ktp) * 2 + 0) * 32 + lane];
            uint4 b2b = Bq2[((qh * 16 + ktp) * 2 + 1) * 32 + lane];
            uint32_t af[4];
            ldmA(af, lmaddr + ktp * 32u);
            mmaf16(acc1[0], af, b1a.x, b1a.y);
            mmaf16(acc1[1], af, b1a.z, b1a.w);
            mmaf16(acc1[2], af, b1b.x, b1b.y);
            mmaf16(acc1[3], af, b1b.z, b1b.w);
            mmaf16(acc2[0], af, b2a.x, b2a.y);
            mmaf16(acc2[1], af, b2a.z, b2a.w);
            mmaf16(acc2[2], af, b2b.x, b2b.y);
            mmaf16(acc2[3], af, b2b.z, b2b.w);
        }
        // ---- k chunks 8..15 : A cols 128:256 = h2(n-2), gates2 only ----
#pragma unroll 2
        for (int ktp = 8; ktp < 16; ktp++) {
            uint4 b2a = Bq2[((qh * 16 + ktp) * 2 + 0) * 32 + lane];
            uint4 b2b = Bq2[((qh * 16 + ktp) * 2 + 1) * 32 + lane];
            uint32_t af[4];
            ldmA(af, lmaddr + ktp * 32u);
            mmaf16(acc2[0], af, b2a.x, b2a.y);
            mmaf16(acc2[1], af, b2a.z, b2a.w);
            mmaf16(acc2[2], af, b2b.x, b2b.y);
            mmaf16(acc2[3], af, b2b.z, b2b.w);
        }

        // ---- epilogue 1: layer-1 cell for t=n ----
        if (n < SEQT) {
#pragma unroll
            for (int rr = 0; rr < 2; rr++) {
                float hv[2];
#pragma unroll
                for (int qq = 0; qq < 2; qq++) {
                    int fr = rr * 2 + qq;
                    int qloc = qh * 8 + tq * 2 + qq;
                    float gi = acc1[0][fr] + xtv[rr] * WX[qloc]      + BB1[qloc];
                    float gf = acc1[1][fr] + xtv[rr] * WX[16 + qloc] + BB1[16 + qloc];
                    float gg = acc1[2][fr] + xtv[rr] * WX[32 + qloc] + BB1[32 + qloc];
                    float go = acc1[3][fr] + xtv[rr] * WX[48 + qloc] + BB1[48 + qloc];
                    float iv = sigfa(gi), fv = sigfa(gf), gv = tanhe(gg), ov = sigfa(go);
                    int ci = rr * 2 + qq;
                    c1[ci] = fv * c1[ci] + iv * gv;
                    hv[qq] = ov * tanhe(c1[ci]);
                }
                __half2 hp = __floats2half2_rn(hv[0], hv[1]);
                ghw[(size_t)(b0 + rows[rr]) * 128 + rank * 8 + qh * 4 + tq] = *(uint32_t*)&hp;
            }
        }
        // ---- epilogue 2: layer-2 cell for t=n-1 ----
        if (n > 0) {
#pragma unroll
            for (int rr = 0; rr < 2; rr++) {
                float hv[2];
#pragma unroll
                for (int qq = 0; qq < 2; qq++) {
                    int fr = rr * 2 + qq;
                    int qloc = qh * 8 + tq * 2 + qq;
                    float gi = acc2[0][fr] + BB2[qloc];
                    float gf = acc2[1][fr] + BB2[16 + qloc];
                    float gg = acc2[2][fr] + BB2[32 + qloc];
                    float go = acc2[3][fr] + BB2[48 + qloc];
                    float iv = sigfa(gi), fv = sigfa(gf), gv = tanhe(gg), ov = sigfa(go);
                    int ci = rr * 2 + qq;
                    c2[ci] = fv * c2[ci] + iv * gv;
                    hv[qq] = ov * tanhe(c2[ci]);
                }
                __half2 hp = __floats2half2_rn(hv[0], hv[1]);
                ghw[(size_t)(b0 + rows[rr]) * 128 + 64 + rank * 8 + qh * 4 + tq] = *(uint32_t*)&hp;
            }
        } else {
            // h2(-1) = 0 (c2 untouched)
#pragma unroll
            for (int e = 0; e < 2; e++)
                ghw[(size_t)(b0 + rows[e]) * 128 + 64 + rank * 8 + qh * 4 + tq] = 0u;
        }

        if (n < SEQT) {
            // exchange: cluster release/acquire orders the STGs vs peers' __ldcg gathers
            CLUSTER_ARRIVE();
            CLUSTER_WAIT();
            // gather full [h1(n) | h2(n-1)] into A tile: 4 threads per row, 8 uint4 each
            {
                const uint4* src = (const uint4*)(ghw + (size_t)(b0 + gr_row) * 128) + gr_q * 8;
                uint4* dst = (uint4*)(sm + OF_A + gr_row * SAW) + gr_q * 8;
#pragma unroll
                for (int j = 0; j < 8; j++) dst[j] = __ldcg(src + j);
            }
            __syncthreads();
        }
    }

    // ---- final linear: out[b] = h2[b,:] . Wl + bl ----
    CLUSTER_ARRIVE();
    CLUSTER_WAIT();
    if (rank == 0 && tid < MROWS) {
        const uint32_t* hr = g_h[SEQT & 1] + (size_t)(b0 + tid) * 128 + 64;
        float acc = bl[0];
#pragma unroll 16
        for (int w = 0; w < 64; w++) {
            uint32_t u = __ldcg(&hr[w]);
            float2 f = __half22float2(*(__half2*)&u);
            acc += f.x * Wl[2 * w] + f.y * Wl[2 * w + 1];
        }
        out[b0 + tid] = acc;
    }
}

// ======================= launch =======================
extern "C" void kernel_launch(void* const* d_in, const int* in_sizes, int n_in,
                              void* d_out, int out_size) {
    const float* x    = (const float*)d_in[0];
    const float* Wih1 = (const float*)d_in[1];
    const float* Whh1 = (const float*)d_in[2];
    const float* bih1 = (const float*)d_in[3];
    const float* bhh1 = (const float*)d_in[4];
    const float* Wih2 = (const float*)d_in[5];
    const float* Whh2 = (const float*)d_in[6];
    const float* bih2 = (const float*)d_in[7];
    const float* bhh2 = (const float*)d_in[8];
    const float* Wl   = (const float*)d_in[9];
    const float* bl   = (const float*)d_in[10];
    float* out = (float*)d_out;

    cudaFuncSetAttribute(lstm2_kernel, cudaFuncAttributeMaxDynamicSharedMemorySize, SMEM_BYTES);

    xT_kernel<<<(BATCH * SEQT + 255) / 256, 256>>>(x);
    lstm2_kernel<<<(BATCH / MROWS) * CL, NTHREADS, SMEM_BYTES>>>(
        Wih1, Whh1, bih1, bhh1, Wih2, Whh2, bih2, bhh2, Wl, bl, out);
}

// round 7
// speedup vs baseline: 1.0005x; 1.0005x over previous
#include <cuda_runtime.h>
#include <cuda_fp16.h>
#include <cstdint>

#define HN       128
#define BATCH    1024
#define SEQT     512
#define CL       8            // CTAs per cluster
#define MROWS    64           // batch rows per cluster
#define NTHREADS 256

#define SAW      132          // A-tile row stride in 32-bit words (264 fp16 = 528 B)

// ---- shared memory layout (32-bit word offsets) ----
#define OF_A     0                       // A tile [64][264 fp16] = 8448 words
#define OF_B1    (64 * SAW)              // layer-1 B frags: 4096 words (16 KB)
#define OF_B2    (OF_B1 + 4096)          // layer-2 B frags: 8192 words (32 KB)
#define OF_WX    (OF_B2 + 8192)          // Wih1 slice   [64] floats
#define OF_BB1   (OF_WX + 64)            // bih1+bhh1    [64] floats
#define OF_BB2   (OF_BB1 + 64)           // bih2+bhh2    [64] floats
#define SMEM_WORDS (OF_BB2 + 64)
#define SMEM_BYTES (SMEM_WORDS * 4)      // 83,712 B

// ---- device scratch (allocation-free) ----
__device__ float    g_xT[SEQT * BATCH];      // x transposed to [T, B]
__device__ uint32_t g_h[2][BATCH * 128];     // double-buffered: per row 128 words = [h1 | h2] fp16

// ======================= helpers =======================
__device__ __forceinline__ uint32_t smem_u32(const void* p) {
    uint32_t a;
    asm("{ .reg .u64 t; cvta.to.shared.u64 t, %1; cvt.u32.u64 %0, t; }" : "=r"(a) : "l"(p));
    return a;
}
#define CLUSTER_ARRIVE() asm volatile("barrier.cluster.arrive.aligned;" ::: "memory")
#define CLUSTER_WAIT()   asm volatile("barrier.cluster.wait.aligned;" ::: "memory")

__device__ __forceinline__ void mmaf16(float* d, const uint32_t* a, uint32_t b0, uint32_t b1) {
    asm volatile(
        "mma.sync.aligned.m16n8k16.row.col.f32.f16.f16.f32 "
        "{%0,%1,%2,%3}, {%4,%5,%6,%7}, {%8,%9}, {%0,%1,%2,%3};"
        : "+f"(d[0]), "+f"(d[1]), "+f"(d[2]), "+f"(d[3])
        : "r"(a[0]), "r"(a[1]), "r"(a[2]), "r"(a[3]), "r"(b0), "r"(b1));
}
__device__ __forceinline__ void ldmA(uint32_t* r, uint32_t addr) {
    asm volatile("ldmatrix.sync.aligned.m8n8.x4.shared.b16 {%0,%1,%2,%3}, [%4];"
                 : "=r"(r[0]), "=r"(r[1]), "=r"(r[2]), "=r"(r[3]) : "r"(addr));
}
// sigmoid via tanh.approx (1 MUFU + 2 FMA); g-gate & cell tanh stay precise
__device__ __forceinline__ float tanha(float x) {
    float y; asm("tanh.approx.f32 %0, %1;" : "=f"(y) : "f"(x)); return y;
}
__device__ __forceinline__ float sigfa(float x) {
    return fmaf(0.5f, tanha(0.5f * x), 0.5f);
}
__device__ __forceinline__ float tanhe(float x) {
    float e = __expf(-2.0f * x);
    return 2.0f * __fdividef(1.0f, 1.0f + e) - 1.0f;
}

// ======================= kernels =======================
__global__ void xT_kernel(const float* __restrict__ x) {
    int i = blockIdx.x * blockDim.x + threadIdx.x;   // i = t*1024 + b (coalesced writes)
    if (i < BATCH * SEQT) {
        int tt = i >> 10, b = i & 1023;
        g_xT[i] = x[b * SEQT + tt];
    }
}

extern "C" __global__ void __launch_bounds__(NTHREADS, 1) __cluster_dims__(CL, 1, 1)
lstm2_kernel(const float* __restrict__ Wih1, const float* __restrict__ Whh1,
             const float* __restrict__ bih1, const float* __restrict__ bhh1,
             const float* __restrict__ Wih2, const float* __restrict__ Whh2,
             const float* __restrict__ bih2, const float* __restrict__ bhh2,
             const float* __restrict__ Wl,   const float* __restrict__ bl,
             float* __restrict__ out)
{
    extern __shared__ uint32_t sm[];
    const int tid  = threadIdx.x;
    const int lane = tid & 31;
    const int wid  = tid >> 5;          // 0..7
    const int g    = lane >> 2;
    const int tq   = lane & 3;
    const int mq   = wid >> 1;          // 0..3 : M16 tile
    const int qh   = wid & 1;           // 0..1 : 8-dim half of the 16-dim slice
    const int mbase = mq * 16;
    const int rank = blockIdx.x & (CL - 1);
    const int b0   = (blockIdx.x / CL) * MROWS;

    float* WX  = (float*)(sm + OF_WX);
    float* BB1 = (float*)(sm + OF_BB1);
    float* BB2 = (float*)(sm + OF_BB2);

    // ---- pack weight slices into fp16 mma-fragment order ----
    // Consumption: uint4 U = ((q2*KTP + ktp)*2 + p)*32 + lane  -> word = 4*U + j
    // decode: j = idx&3, lane = (idx>>2)&31, p = (idx>>7)&1, ktp next, q2 top.
    // Fragment: gate = p*2 + (j>>1), reg = j&1;
    // B[k][n]: k0 = ktp*16 + reg*8 + 2*(lane&3), n = q2*8 + (lane>>2)
    for (int idx = tid; idx < 4096; idx += NTHREADS) {          // layer 1 (K=128)
        int j = idx & 3, ln = (idx >> 2) & 31, p = (idx >> 7) & 1;
        int ktp = (idx >> 8) & 7, q2 = idx >> 11;
        int gate = p * 2 + (j >> 1), reg = j & 1;
        int gg = ln >> 2, ttq = ln & 3;
        int k0 = ktp * 16 + reg * 8 + 2 * ttq;
        int gr = gate * HN + rank * 16 + q2 * 8 + gg;
        __half2 hv = __floats2half2_rn(Whh1[gr * HN + k0], Whh1[gr * HN + k0 + 1]);
        sm[OF_B1 + idx] = *(uint32_t*)&hv;
    }
    for (int idx = tid; idx < 8192; idx += NTHREADS) {          // layer 2 (K=256)
        int j = idx & 3, ln = (idx >> 2) & 31, p = (idx >> 7) & 1;
        int ktp = (idx >> 8) & 15, q2 = idx >> 12;
        int gate = p * 2 + (j >> 1), reg = j & 1;
        int gg = ln >> 2, ttq = ln & 3;
        int k0 = ktp * 16 + reg * 8 + 2 * ttq;
        int gr = gate * HN + rank * 16 + q2 * 8 + gg;
        float w0 = (k0 < HN)     ? Wih2[gr * HN + k0]     : Whh2[gr * HN + k0 - HN];
        float w1 = (k0 + 1 < HN) ? Wih2[gr * HN + k0 + 1] : Whh2[gr * HN + k0 + 1 - HN];
        __half2 hv = __floats2half2_rn(w0, w1);
        sm[OF_B2 + idx] = *(uint32_t*)&hv;
    }
    if (tid < 64) {
        int gt = tid >> 4, q = tid & 15;
        int gr = gt * HN + rank * 16 + q;
        WX[tid]  = Wih1[gr];
        BB1[tid] = bih1[gr] + bhh1[gr];
        BB2[tid] = bih2[gr] + bhh2[gr];
    }
    for (int i = tid; i < 64 * SAW; i += NTHREADS) sm[OF_A + i] = 0u;   // h1=h2=0
    __syncthreads();

    // per-thread rows (2 per layer-tile) and ldmatrix address
    int rows[2];
    rows[0] = mbase + g;
    rows[1] = mbase + g + 8;

    const uint32_t sbA = smem_u32(sm) + OF_A * 4;
    const int row_in = mbase + (lane & 7) + ((lane >> 3) & 1) * 8;
    const uint32_t lmaddr = sbA + (uint32_t)row_in * 528u + ((lane >> 4) & 1) * 16u;

    const uint4* Bq1 = (const uint4*)(sm + OF_B1);
    const uint4* Bq2 = (const uint4*)(sm + OF_B2);

    float c1[4], c2[4];
#pragma unroll
    for (int i = 0; i < 4; i++) { c1[i] = 0.f; c2[i] = 0.f; }

    // gather indices: 4 threads per row, 8 uint4 each
    const int gr_row = tid >> 2, gr_q = tid & 3;

    for (int n = 0; n <= SEQT; n++) {
        uint32_t* ghw = g_h[n & 1];     // this iteration's exchange buffer

        // prefetch x(n) early (consumed after MMA)
        float xtv[2];
        if (n < SEQT) {
#pragma unroll
            for (int e = 0; e < 2; e++) xtv[e] = __ldcg(&g_xT[n * BATCH + b0 + rows[e]]);
        }

        float acc1[4][4], acc2[4][4];
#pragma unroll
        for (int a1 = 0; a1 < 4; a1++)
#pragma unroll
            for (int a3 = 0; a3 < 4; a3++) { acc1[a1][a3] = 0.f; acc2[a1][a3] = 0.f; }

        // ---- k chunks 0..7 : A cols 0:128 = h1(n-1), feeds gates1 AND gates2 ----
#pragma unroll 2
        for (int ktp = 0; ktp < 8; ktp++) {
            uint4 b1a = Bq1[((qh * 8 + ktp) * 2 + 0) * 32 + lane];
            uint4 b1b = Bq1[((qh * 8 + ktp) * 2 + 1) * 32 + lane];
            uint4 b2a = Bq2[((qh * 16 + ktp) * 2 + 0) * 32 + lane];
            uint4 b2b = Bq2[((qh * 16 + ktp) * 2 + 1) * 32 + lane];
            uint32_t af[4];
            ldmA(af, lmaddr + ktp * 32u);
            mmaf16(acc1[0], af, b1a.x, b1a.y);
            mmaf16(acc1[1], af, b1a.z, b1a.w);
            mmaf16(acc1[2], af, b1b.x, b1b.y);
            mmaf16(acc1[3], af, b1b.z, b1b.w);
            mmaf16(acc2[0], af, b2a.x, b2a.y);
            mmaf16(acc2[1], af, b2a.z, b2a.w);
            mmaf16(acc2[2], af, b2b.x, b2b.y);
            mmaf16(acc2[3], af, b2b.z, b2b.w);
        }
        // ---- k chunks 8..15 : A cols 128:256 = h2(n-2), gates2 only ----
#pragma unroll 2
        for (int ktp = 8; ktp < 16; ktp++) {
            uint4 b2a = Bq2[((qh * 16 + ktp) * 2 + 0) * 32 + lane];
            uint4 b2b = Bq2[((qh * 16 + ktp) * 2 + 1) * 32 + lane];
            uint32_t af[4];
            ldmA(af, lmaddr + ktp * 32u);
            mmaf16(acc2[0], af, b2a.x, b2a.y);
            mmaf16(acc2[1], af, b2a.z, b2a.w);
            mmaf16(acc2[2], af, b2b.x, b2b.y);
            mmaf16(acc2[3], af, b2b.z, b2b.w);
        }

        // ---- epilogue 1: layer-1 cell for t=n ----
        if (n < SEQT) {
#pragma unroll
            for (int rr = 0; rr < 2; rr++) {
                float hv[2];
#pragma unroll
                for (int qq = 0; qq < 2; qq++) {
                    int fr = rr * 2 + qq;
                    int qloc = qh * 8 + tq * 2 + qq;
                    float gi = acc1[0][fr] + xtv[rr] * WX[qloc]      + BB1[qloc];
                    float gf = acc1[1][fr] + xtv[rr] * WX[16 + qloc] + BB1[16 + qloc];
                    float gg = acc1[2][fr] + xtv[rr] * WX[32 + qloc] + BB1[32 + qloc];
                    float go = acc1[3][fr] + xtv[rr] * WX[48 + qloc] + BB1[48 + qloc];
                    float iv = sigfa(gi), fv = sigfa(gf), gv = tanhe(gg), ov = sigfa(go);
                    int ci = rr * 2 + qq;
                    c1[ci] = fv * c1[ci] + iv * gv;
                    hv[qq] = ov * tanhe(c1[ci]);
                }
                __half2 hp = __floats2half2_rn(hv[0], hv[1]);
                ghw[(size_t)(b0 + rows[rr]) * 128 + rank * 8 + qh * 4 + tq] = *(uint32_t*)&hp;
            }
        }
        // ---- epilogue 2: layer-2 cell for t=n-1 ----
        if (n > 0) {
#pragma unroll
            for (int rr = 0; rr < 2; rr++) {
                float hv[2];
#pragma unroll
                for (int qq = 0; qq < 2; qq++) {
                    int fr = rr * 2 + qq;
                    int qloc = qh * 8 + tq * 2 + qq;
                    float gi = acc2[0][fr] + BB2[qloc];
                    float gf = acc2[1][fr] + BB2[16 + qloc];
                    float gg = acc2[2][fr] + BB2[32 + qloc];
                    float go = acc2[3][fr] + BB2[48 + qloc];
                    float iv = sigfa(gi), fv = sigfa(gf), gv = tanhe(gg), ov = sigfa(go);
                    int ci = rr * 2 + qq;
                    c2[ci] = fv * c2[ci] + iv * gv;
                    hv[qq] = ov * tanhe(c2[ci]);
                }
                __half2 hp = __floats2half2_rn(hv[0], hv[1]);
                ghw[(size_t)(b0 + rows[rr]) * 128 + 64 + rank * 8 + qh * 4 + tq] = *(uint32_t*)&hp;
            }
        } else {
            // h2(-1) = 0 (c2 untouched)
#pragma unroll
            for (int e = 0; e < 2; e++)
                ghw[(size_t)(b0 + rows[e]) * 128 + 64 + rank * 8 + qh * 4 + tq] = 0u;
        }

        if (n < SEQT) {
            // exchange: cluster release/acquire orders the STGs vs peers' __ldcg gathers
            CLUSTER_ARRIVE();
            CLUSTER_WAIT();
            // gather full [h1(n) | h2(n-1)] into A tile: 4 threads per row, 8 uint4 each
            {
                const uint4* src = (const uint4*)(ghw + (size_t)(b0 + gr_row) * 128) + gr_q * 8;
                uint4* dst = (uint4*)(sm + OF_A + gr_row * SAW) + gr_q * 8;
#pragma unroll
                for (int j = 0; j < 8; j++) dst[j] = __ldcg(src + j);
            }
            __syncthreads();
        }
    }

    // ---- final linear: out[b] = h2[b,:] . Wl + bl ----
    CLUSTER_ARRIVE();
    CLUSTER_WAIT();
    if (rank == 0 && tid < MROWS) {
        const uint32_t* hr = g_h[SEQT & 1] + (size_t)(b0 + tid) * 128 + 64;
        float acc = bl[0];
#pragma unroll 16
        for (int w = 0; w < 64; w++) {
            uint32_t u = __ldcg(&hr[w]);
            float2 f = __half22float2(*(__half2*)&u);
            acc += f.x * Wl[2 * w] + f.y * Wl[2 * w + 1];
        }
        out[b0 + tid] = acc;
    }
}

// ======================= launch =======================
extern "C" void kernel_launch(void* const* d_in, const int* in_sizes, int n_in,
                              void* d_out, int out_size) {
    const float* x    = (const float*)d_in[0];
    const float* Wih1 = (const float*)d_in[1];
    const float* Whh1 = (const float*)d_in[2];
    const float* bih1 = (const float*)d_in[3];
    const float* bhh1 = (const float*)d_in[4];
    const float* Wih2 = (const float*)d_in[5];
    const float* Whh2 = (const float*)d_in[6];
    const float* bih2 = (const float*)d_in[7];
    const float* bhh2 = (const float*)d_in[8];
    const float* Wl   = (const float*)d_in[9];
    const float* bl   = (const float*)d_in[10];
    float* out = (float*)d_out;

    cudaFuncSetAttribute(lstm2_kernel, cudaFuncAttributeMaxDynamicSharedMemorySize, SMEM_BYTES);

    xT_kernel<<<(BATCH * SEQT + 255) / 256, 256>>>(x);
    lstm2_kernel<<<(BATCH / MROWS) * CL, NTHREADS, SMEM_BYTES>>>(
        Wih1, Whh1, bih1, bhh1, Wih2, Whh2, bih2, bhh2, Wl, bl, out);
}